// round 4
// baseline (speedup 1.0000x reference)
#include <cuda_runtime.h>

#define BB 512
#define TT 1024
#define HH 100
#define VV 62

typedef unsigned long long ull;

// ping-pong time-major [T][B][H] activation buffers (no cudaMalloc allowed)
__device__ float g_bufA[(size_t)TT * BB * HH];
__device__ float g_bufB[(size_t)TT * BB * HH];

// packed dual-fp32 FMA: d.lo += a.lo*b.lo ; d.hi += a.hi*b.hi
__device__ __forceinline__ void fma2(ull& d, ull a, ull b) {
    asm("fma.rn.f32x2 %0, %1, %2, %0;" : "+l"(d) : "l"(a), "l"(b));
}
__device__ __forceinline__ float red2(ull v) {
    return __uint_as_float((unsigned)v) + __uint_as_float((unsigned)(v >> 32));
}
// fast tanh: 1 - 2/(e^{2x}+1); __expf saturates to inf -> result -> 1. OK.
__device__ __forceinline__ float ftanh(float x) {
    float e = __expf(x + x);
    return 1.0f - __fdividef(2.0f, e + 1.0f);
}

// ---------------------------------------------------------------------------
// 1) embedding gather (split in two launches so ncu -s5 lands on rnn#2):
//    x[t][b][:] = emb[ids[b][t]][:]  (time-major out)
// ---------------------------------------------------------------------------
__global__ void k_gather(const int* __restrict__ ids,
                         const float* __restrict__ emb,
                         float* __restrict__ out, int base) {
    int idx = base + blockIdx.x * blockDim.x + threadIdx.x;  // over T*B*25 f4
    if (idx >= TT * BB * 25) return;
    int c  = idx % 25;
    int tb = idx / 25;
    int b  = tb % BB;
    int t  = tb / BB;
    int id = ids[(size_t)b * TT + t];
    float4 v = ((const float4*)(emb + (size_t)id * HH))[c];
    ((float4*)(out + ((size_t)t * BB + b) * HH))[c] = v;
}

// ---------------------------------------------------------------------------
// 2) input projection: Y[row][k] = sum_j X[row][j]*W[k][j] + bi[k] + bh[k]
// K8 x R4 register tile. Block = 416 thr = 13 warps; kq = tid/32 is
// WARP-UNIFORM -> all 8 W loads/j4 are full-warp broadcasts (1 wavefront).
// rows = 128/block, r = (tid%32) + 32*rr -> consecutive-lane rows,
// stride 25 f4 (odd) -> conflict-free X loads. k padded 100->104.
// ---------------------------------------------------------------------------
#define PROJ_T 416
#define PROJ_ROWS 128
__global__ void __launch_bounds__(PROJ_T, 1) k_proj(const float* __restrict__ X,
                                                    const float* __restrict__ W,
                                                    const float* __restrict__ bi,
                                                    const float* __restrict__ bh,
                                                    float* __restrict__ Y) {
    extern __shared__ float sm[];
    float* Ws = sm;             // [104][100]
    float* Xs = sm + 10400;     // [128][100]
    float* bs = sm + 23200;     // [104]

    int tid = threadIdx.x;
    float4* Ws4 = (float4*)Ws;
    const float4* Wg = (const float4*)W;
    for (int i = tid; i < 2600; i += PROJ_T) {      // 104*25
        int k = i / 25;
        float4 z = {0.f, 0.f, 0.f, 0.f};
        Ws4[i] = (k < HH) ? Wg[i] : z;
    }
    if (tid < 104) bs[tid] = (tid < HH) ? (bi[tid] + bh[tid]) : 0.f;

    size_t row0 = (size_t)blockIdx.x * PROJ_ROWS;
    float4* Xs4 = (float4*)Xs;
    const float4* Xg = (const float4*)X;
    for (int i = tid; i < PROJ_ROWS * 25; i += PROJ_T) Xs4[i] = Xg[row0 * 25 + i];
    __syncthreads();

    int kq = tid / 32;          // 0..12, warp-uniform
    int rg = tid % 32;
    int k0 = kq * 8;

    const ulonglong2* Wu = (const ulonglong2*)Ws;   // [k][j4] pairs, 25/row
    const ulonglong2* Xu = (const ulonglong2*)Xs;

    ull acc[8][4];
#pragma unroll
    for (int c = 0; c < 8; c++)
#pragma unroll
        for (int r = 0; r < 4; r++) acc[c][r] = 0ull;

#pragma unroll 5
    for (int j4 = 0; j4 < 25; j4++) {
        ulonglong2 x0 = Xu[(rg +  0) * 25 + j4];
        ulonglong2 x1 = Xu[(rg + 32) * 25 + j4];
        ulonglong2 x2 = Xu[(rg + 64) * 25 + j4];
        ulonglong2 x3 = Xu[(rg + 96) * 25 + j4];
#pragma unroll
        for (int c = 0; c < 8; c++) {
            ulonglong2 w = Wu[(k0 + c) * 25 + j4];  // warp-broadcast
            fma2(acc[c][0], w.x, x0.x); fma2(acc[c][0], w.y, x0.y);
            fma2(acc[c][1], w.x, x1.x); fma2(acc[c][1], w.y, x1.y);
            fma2(acc[c][2], w.x, x2.x); fma2(acc[c][2], w.y, x2.y);
            fma2(acc[c][3], w.x, x3.x); fma2(acc[c][3], w.y, x3.y);
        }
    }

    float bb[8];
#pragma unroll
    for (int c = 0; c < 8; c++) bb[c] = bs[k0 + c];

    float4* Yg = (float4*)Y;
#pragma unroll
    for (int rr = 0; rr < 4; rr++) {
        size_t row = row0 + rg + 32 * rr;
        float4 o;
        o.x = red2(acc[0][rr]) + bb[0];
        o.y = red2(acc[1][rr]) + bb[1];
        o.z = red2(acc[2][rr]) + bb[2];
        o.w = red2(acc[3][rr]) + bb[3];
        Yg[row * 25 + kq * 2] = o;
        if (kq < 12) {                      // k4..k7 < 100 only for kq<12
            float4 o2;
            o2.x = red2(acc[4][rr]) + bb[4];
            o2.y = red2(acc[5][rr]) + bb[5];
            o2.z = red2(acc[6][rr]) + bb[6];
            o2.w = red2(acc[7][rr]) + bb[7];
            Yg[row * 25 + kq * 2 + 1] = o2;
        }
    }
}

// ---------------------------------------------------------------------------
// 3) recurrent scan: h_new = tanh(xin[t] + h @ Wh^T), in-place on XY.
// 128 blocks x 4 batch rows x 128 threads -> exactly 1 block/SM, balanced.
// Thread k holds W[k][:] in 100 regs (launch_bounds(128,1): no spill).
// h via smem broadcast; ONE barrier/step; global stores post-barrier.
// ---------------------------------------------------------------------------
__global__ void __launch_bounds__(128, 1) k_rnn(float* __restrict__ XY,
                                                const float* __restrict__ W,
                                                float* __restrict__ hout) {
    __shared__ __align__(16) float hs[2][4][104];

    int tid = threadIdx.x;
    int kk = (tid < HH) ? tid : (HH - 1);

    ulonglong2 wv[25];                      // W[kk][0..99]
    const ulonglong2* Wg = (const ulonglong2*)W;
#pragma unroll
    for (int i = 0; i < 25; i++) wv[i] = Wg[kk * 25 + i];

    if (tid < 104) {
        hs[0][0][tid] = 0.f; hs[0][1][tid] = 0.f;
        hs[0][2][tid] = 0.f; hs[0][3][tid] = 0.f;
    }
    __syncthreads();

    int b0 = blockIdx.x * 4;
    const size_t st = (size_t)BB * HH;
    const float* px = XY + (size_t)b0 * HH + kk;

    float c0 = px[0], c1 = px[HH], c2 = px[2 * HH], c3 = px[3 * HH];
    int p = 0;

    for (int t = 0; t < TT; t++) {
        size_t tn = (size_t)((t + 1 < TT) ? t + 1 : t) * st;
        float n0 = px[tn], n1 = px[tn + HH], n2 = px[tn + 2 * HH], n3 = px[tn + 3 * HH];

        ull a0l = 0, a0h = 0, a1l = 0, a1h = 0;
        ull a2l = 0, a2h = 0, a3l = 0, a3h = 0;
        const ulonglong2* h0p = (const ulonglong2*)&hs[p][0][0];
        const ulonglong2* h1p = (const ulonglong2*)&hs[p][1][0];
        const ulonglong2* h2p = (const ulonglong2*)&hs[p][2][0];
        const ulonglong2* h3p = (const ulonglong2*)&hs[p][3][0];
#pragma unroll
        for (int j = 0; j < 25; j++) {
            ulonglong2 w = wv[j];
            ulonglong2 h0 = h0p[j];          // broadcast loads (1 wf each)
            ulonglong2 h1 = h1p[j];
            ulonglong2 h2 = h2p[j];
            ulonglong2 h3 = h3p[j];
            fma2(a0l, w.x, h0.x); fma2(a0h, w.y, h0.y);
            fma2(a1l, w.x, h1.x); fma2(a1h, w.y, h1.y);
            fma2(a2l, w.x, h2.x); fma2(a2h, w.y, h2.y);
            fma2(a3l, w.x, h3.x); fma2(a3h, w.y, h3.y);
        }
        float z0 = ftanh(red2(a0l) + red2(a0h) + c0);
        float z1 = ftanh(red2(a1l) + red2(a1h) + c1);
        float z2 = ftanh(red2(a2l) + red2(a2h) + c2);
        float z3 = ftanh(red2(a3l) + red2(a3h) + c3);

        if (tid < HH) {
            hs[p ^ 1][0][tid] = z0;
            hs[p ^ 1][1][tid] = z1;
            hs[p ^ 1][2][tid] = z2;
            hs[p ^ 1][3][tid] = z3;
        }
        __syncthreads();

        if (tid < HH) {                      // off critical path: post-barrier
            float* py = XY + (size_t)t * st + (size_t)b0 * HH + tid;
            py[0] = z0; py[HH] = z1; py[2 * HH] = z2; py[3 * HH] = z3;
        }
        p ^= 1;
        c0 = n0; c1 = n1; c2 = n2; c3 = n3;
    }

    if (tid < HH) {
#pragma unroll
        for (int r = 0; r < 4; r++)
            hout[(size_t)(b0 + r) * HH + tid] = hs[p][r][tid];
    }
}

// ---------------------------------------------------------------------------
// 4) decoder: logits[b][t][v] = dot(ys[t][b][:], Wd[v][:]) + bd[v]
// 256 thr = 16 v-quads (vq=tid/16, V padded 64) x 16 row-groups, 64 rows/blk.
// ---------------------------------------------------------------------------
__global__ void __launch_bounds__(256, 3) k_dec(const float* __restrict__ Ys,
                                                const float* __restrict__ Wd,
                                                const float* __restrict__ bd,
                                                float* __restrict__ out) {
    extern __shared__ float sm[];
    float* Ws = sm;            // [64][100] zero-padded
    float* Xs = sm + 6400;     // [64][100]
    float* bs = sm + 12800;    // [64]

    int tid = threadIdx.x;
    for (int i = tid; i < 6400; i += 256) Ws[i] = (i < VV * HH) ? Wd[i] : 0.f;
    if (tid < 64) bs[tid] = (tid < VV) ? bd[tid] : 0.f;

    size_t row0 = (size_t)blockIdx.x * 64;
    float4* Xs4 = (float4*)Xs;
    const float4* Yg = (const float4*)Ys;
    for (int i = tid; i < 1600; i += 256) Xs4[i] = Yg[row0 * 25 + i];
    __syncthreads();

    int vq = tid / 16;   // 0..15
    int rg = tid % 16;

    const ulonglong2* Wu = (const ulonglong2*)Ws;
    const ulonglong2* Xu = (const ulonglong2*)Xs;

    ull acc[4][4];
#pragma unroll
    for (int c = 0; c < 4; c++)
#pragma unroll
        for (int r = 0; r < 4; r++) acc[c][r] = 0ull;

#pragma unroll 5
    for (int j4 = 0; j4 < 25; j4++) {
        ulonglong2 x0 = Xu[(rg +  0) * 25 + j4];
        ulonglong2 x1 = Xu[(rg + 16) * 25 + j4];
        ulonglong2 x2 = Xu[(rg + 32) * 25 + j4];
        ulonglong2 x3 = Xu[(rg + 48) * 25 + j4];
#pragma unroll
        for (int c = 0; c < 4; c++) {
            ulonglong2 w = Wu[(vq * 4 + c) * 25 + j4];
            fma2(acc[c][0], w.x, x0.x); fma2(acc[c][0], w.y, x0.y);
            fma2(acc[c][1], w.x, x1.x); fma2(acc[c][1], w.y, x1.y);
            fma2(acc[c][2], w.x, x2.x); fma2(acc[c][2], w.y, x2.y);
            fma2(acc[c][3], w.x, x3.x); fma2(acc[c][3], w.y, x3.y);
        }
    }

    int v0 = vq * 4;
    float bb0 = bs[v0], bb1 = bs[v0 + 1], bb2 = bs[v0 + 2], bb3 = bs[v0 + 3];
#pragma unroll
    for (int rr = 0; rr < 4; rr++) {
        size_t row = row0 + rg + 16 * rr;   // = t*BB + b
        size_t t = row >> 9;
        size_t b = row & 511;
        float* o = out + (b * TT + t) * VV + v0;
        o[0] = red2(acc[0][rr]) + bb0;
        o[1] = red2(acc[1][rr]) + bb1;
        if (v0 + 2 < VV) {
            o[2] = red2(acc[2][rr]) + bb2;
            o[3] = red2(acc[3][rr]) + bb3;
        }
    }
}

// ---------------------------------------------------------------------------
extern "C" void kernel_launch(void* const* d_in, const int* in_sizes, int n_in,
                              void* d_out, int out_size) {
    const int*   ids   = (const int*)d_in[0];
    const float* emb   = (const float*)d_in[1];
    const float* W_ih  = (const float*)d_in[2];   // [3][100][100]
    const float* W_hh  = (const float*)d_in[3];   // [3][100][100]
    const float* b_ih  = (const float*)d_in[4];   // [3][100]
    const float* b_hh  = (const float*)d_in[5];   // [3][100]
    const float* W_dec = (const float*)d_in[6];   // [62][100]
    const float* b_dec = (const float*)d_in[7];   // [62]
    float* out = (float*)d_out;

    float *bufA, *bufB;
    cudaGetSymbolAddress((void**)&bufA, g_bufA);
    cudaGetSymbolAddress((void**)&bufB, g_bufB);

    const int proj_smem = 23304 * (int)sizeof(float);   // ~93 KB
    const int dec_smem  = 12864 * (int)sizeof(float);   // ~50 KB
    cudaFuncSetAttribute(k_proj, cudaFuncAttributeMaxDynamicSharedMemorySize, proj_smem);
    cudaFuncSetAttribute(k_dec,  cudaFuncAttributeMaxDynamicSharedMemorySize, dec_smem);

    float* hid = out + (size_t)BB * TT * VV;
    const int NPROJ = (TT * BB) / PROJ_ROWS;   // 4096
    const int NDEC  = (TT * BB) / 64;          // 8192

    // gather split into 2 launches (profiling alignment: launch idx5 = rnn#2)
    {
        int total = TT * BB * 25;
        int half = total / 2;
        k_gather<<<(half + 255) / 256, 256>>>(ids, emb, bufA, 0);
        k_gather<<<(total - half + 255) / 256, 256>>>(ids, emb, bufA, half);
    }

    // layer 0
    k_proj<<<NPROJ, PROJ_T, proj_smem>>>(bufA, W_ih, b_ih, b_hh, bufB);
    k_rnn<<<BB / 4, 128>>>(bufB, W_hh, hid);
    // layer 1
    k_proj<<<NPROJ, PROJ_T, proj_smem>>>(bufB, W_ih + 10000, b_ih + 100, b_hh + 100, bufA);
    k_rnn<<<BB / 4, 128>>>(bufA, W_hh + 10000, hid + (size_t)BB * HH);
    // layer 2
    k_proj<<<NPROJ, PROJ_T, proj_smem>>>(bufA, W_ih + 20000, b_ih + 200, b_hh + 200, bufB);
    k_rnn<<<BB / 4, 128>>>(bufB, W_hh + 20000, hid + 2 * (size_t)BB * HH);

    k_dec<<<NDEC, 256, dec_smem>>>(bufB, W_dec, b_dec, out);
}

// round 5
// speedup vs baseline: 1.4815x; 1.4815x over previous
#include <cuda_runtime.h>

#define BB 512
#define TT 1024
#define HH 100
#define VV 62

typedef unsigned long long ull;

// ping-pong time-major [T][B][H] activation buffers (no cudaMalloc allowed)
__device__ float g_bufA[(size_t)TT * BB * HH];
__device__ float g_bufB[(size_t)TT * BB * HH];

// packed dual-fp32 FMA: d.lo += a.lo*b.lo ; d.hi += a.hi*b.hi
__device__ __forceinline__ void fma2(ull& d, ull a, ull b) {
    asm("fma.rn.f32x2 %0, %1, %2, %0;" : "+l"(d) : "l"(a), "l"(b));
}
__device__ __forceinline__ float red2(ull v) {
    return __uint_as_float((unsigned)v) + __uint_as_float((unsigned)(v >> 32));
}
// fast tanh: 1 - 2/(e^{2x}+1); __expf saturates to inf -> result -> 1. OK.
__device__ __forceinline__ float ftanh(float x) {
    float e = __expf(x + x);
    return 1.0f - __fdividef(2.0f, e + 1.0f);
}

// ---------------------------------------------------------------------------
// 1) embedding gather (2 launches so ncu -s5 lands on rnn#2):
// ---------------------------------------------------------------------------
__global__ void k_gather(const int* __restrict__ ids,
                         const float* __restrict__ emb,
                         float* __restrict__ out, int base) {
    int idx = base + blockIdx.x * blockDim.x + threadIdx.x;  // T*B*25 f4
    if (idx >= TT * BB * 25) return;
    int c  = idx % 25;
    int tb = idx / 25;
    int b  = tb % BB;
    int t  = tb / BB;
    int id = ids[(size_t)b * TT + t];
    float4 v = ((const float4*)(emb + (size_t)id * HH))[c];
    ((float4*)(out + ((size_t)t * BB + b) * HH))[c] = v;
}

// ---------------------------------------------------------------------------
// 2) input projection: Y[row][k] = sum_j X[row][j]*W[k][j] + bi[k] + bh[k]
// K8 x R2 tile, 64 rows/block, 416 thr (13 warps), OCC 2 (67KB smem).
// kq = tid/32 warp-uniform -> 8 W loads/j4 are warp-broadcasts (1 wf each);
// X loads stride 100 words -> conflict-free. 16 wf : 16 FMA-cyc per j4.
// ---------------------------------------------------------------------------
#define PROJ_T 416
#define PROJ_ROWS 64
__global__ void __launch_bounds__(PROJ_T, 2) k_proj(const float* __restrict__ X,
                                                    const float* __restrict__ W,
                                                    const float* __restrict__ bi,
                                                    const float* __restrict__ bh,
                                                    float* __restrict__ Y) {
    extern __shared__ float sm[];
    float* Ws = sm;             // [104][100] zero-padded rows 100..103
    float* Xs = sm + 10400;     // [64][100]
    float* bs = sm + 16800;     // [104]

    int tid = threadIdx.x;
    float4* Ws4 = (float4*)Ws;
    const float4* Wg = (const float4*)W;
    for (int i = tid; i < 2600; i += PROJ_T) {      // 104*25
        int k = i / 25;
        float4 z = {0.f, 0.f, 0.f, 0.f};
        Ws4[i] = (k < HH) ? Wg[i] : z;
    }
    if (tid < 104) bs[tid] = (tid < HH) ? (bi[tid] + bh[tid]) : 0.f;

    size_t row0 = (size_t)blockIdx.x * PROJ_ROWS;
    float4* Xs4 = (float4*)Xs;
    const float4* Xg = (const float4*)X;
    for (int i = tid; i < PROJ_ROWS * 25; i += PROJ_T) Xs4[i] = Xg[row0 * 25 + i];
    __syncthreads();

    int kq = tid / 32;          // 0..12, warp-uniform
    int rg = tid % 32;
    int k0 = kq * 8;

    const ulonglong2* Wu = (const ulonglong2*)Ws;   // 25 pairs per k-row
    const ulonglong2* Xu = (const ulonglong2*)Xs;

    ull acc[8][2];
#pragma unroll
    for (int c = 0; c < 8; c++) { acc[c][0] = 0ull; acc[c][1] = 0ull; }

#pragma unroll 5
    for (int j4 = 0; j4 < 25; j4++) {
        ulonglong2 x0 = Xu[(rg +  0) * 25 + j4];
        ulonglong2 x1 = Xu[(rg + 32) * 25 + j4];
#pragma unroll
        for (int c = 0; c < 8; c++) {
            ulonglong2 w = Wu[(k0 + c) * 25 + j4];  // warp-broadcast
            fma2(acc[c][0], w.x, x0.x); fma2(acc[c][0], w.y, x0.y);
            fma2(acc[c][1], w.x, x1.x); fma2(acc[c][1], w.y, x1.y);
        }
    }

    float bb[8];
#pragma unroll
    for (int c = 0; c < 8; c++) bb[c] = bs[k0 + c];

    float4* Yg = (float4*)Y;
#pragma unroll
    for (int rr = 0; rr < 2; rr++) {
        size_t row = row0 + rg + 32 * rr;
        float4 o;
        o.x = red2(acc[0][rr]) + bb[0];
        o.y = red2(acc[1][rr]) + bb[1];
        o.z = red2(acc[2][rr]) + bb[2];
        o.w = red2(acc[3][rr]) + bb[3];
        Yg[row * 25 + kq * 2] = o;
        if (kq < 12) {
            float4 o2;
            o2.x = red2(acc[4][rr]) + bb[4];
            o2.y = red2(acc[5][rr]) + bb[5];
            o2.z = red2(acc[6][rr]) + bb[6];
            o2.w = red2(acc[7][rr]) + bb[7];
            Yg[row * 25 + kq * 2 + 1] = o2;
        }
    }
}

// ---------------------------------------------------------------------------
// 3) recurrent scan: h_new = tanh(xin[t] + h @ Wh^T), in-place on XY.
// 128 blocks (exactly 1/SM) x 256 threads = two independent 128-thread
// groups, each owning 2 batch rows -> 4 rows/block, 8 warps/SM, balanced.
// Thread k holds W[k][:] in 100 regs; h via smem broadcast; 1 barrier/step.
// ---------------------------------------------------------------------------
__global__ void __launch_bounds__(256, 1) k_rnn(float* __restrict__ XY,
                                                const float* __restrict__ W,
                                                float* __restrict__ hout) {
    __shared__ __align__(16) float hs[2][4][104];

    int tid = threadIdx.x;
    int g   = tid >> 7;          // row-group 0/1
    int k   = tid & 127;
    int kk  = (k < HH) ? k : (HH - 1);
    int r0  = g * 2;

    ulonglong2 wv[25];           // W[kk][0..99]
    const ulonglong2* Wg = (const ulonglong2*)W;
#pragma unroll
    for (int i = 0; i < 25; i++) wv[i] = Wg[kk * 25 + i];

    if (tid < 104) {
        hs[0][0][tid] = 0.f; hs[0][1][tid] = 0.f;
        hs[0][2][tid] = 0.f; hs[0][3][tid] = 0.f;
    }
    __syncthreads();

    int b0 = blockIdx.x * 4 + r0;            // this group's first batch row
    const size_t st = (size_t)BB * HH;
    const float* px = XY + (size_t)b0 * HH + kk;

    float c0 = px[0], c1 = px[HH];
    int p = 0;

    for (int t = 0; t < TT; t++) {
        size_t tn = (size_t)((t + 1 < TT) ? t + 1 : t) * st;
        float n0 = px[tn], n1 = px[tn + HH];  // prefetch next xin

        ull a0l = 0, a0h = 0, a1l = 0, a1h = 0;
        const ulonglong2* h0p = (const ulonglong2*)&hs[p][r0][0];
        const ulonglong2* h1p = (const ulonglong2*)&hs[p][r0 + 1][0];
#pragma unroll
        for (int j = 0; j < 25; j++) {
            ulonglong2 w  = wv[j];
            ulonglong2 h0 = h0p[j];           // broadcast loads
            ulonglong2 h1 = h1p[j];
            fma2(a0l, w.x, h0.x); fma2(a0h, w.y, h0.y);
            fma2(a1l, w.x, h1.x); fma2(a1h, w.y, h1.y);
        }
        float z0 = ftanh(red2(a0l) + red2(a0h) + c0);
        float z1 = ftanh(red2(a1l) + red2(a1h) + c1);

        if (k < HH) {
            hs[p ^ 1][r0][k]     = z0;
            hs[p ^ 1][r0 + 1][k] = z1;
            float* py = XY + (size_t)t * st + (size_t)b0 * HH + k;
            py[0] = z0; py[HH] = z1;
        }
        __syncthreads();
        p ^= 1;
        c0 = n0; c1 = n1;
    }

    if (k < HH) {
        hout[(size_t)b0 * HH + k]       = hs[p][r0][k];
        hout[(size_t)(b0 + 1) * HH + k] = hs[p][r0 + 1][k];
    }
}

// ---------------------------------------------------------------------------
// 4) decoder: logits[b][t][v] = dot(ys[t][b][:], Wd[v][:]) + bd[v]
// 256 thr = 16 v-quads (vq=tid/16, V padded 64) x 16 row-groups, 64 rows/blk.
// ---------------------------------------------------------------------------
__global__ void __launch_bounds__(256, 3) k_dec(const float* __restrict__ Ys,
                                                const float* __restrict__ Wd,
                                                const float* __restrict__ bd,
                                                float* __restrict__ out) {
    extern __shared__ float sm[];
    float* Ws = sm;            // [64][100] zero-padded
    float* Xs = sm + 6400;     // [64][100]
    float* bs = sm + 12800;    // [64]

    int tid = threadIdx.x;
    for (int i = tid; i < 6400; i += 256) Ws[i] = (i < VV * HH) ? Wd[i] : 0.f;
    if (tid < 64) bs[tid] = (tid < VV) ? bd[tid] : 0.f;

    size_t row0 = (size_t)blockIdx.x * 64;
    float4* Xs4 = (float4*)Xs;
    const float4* Yg = (const float4*)Ys;
    for (int i = tid; i < 1600; i += 256) Xs4[i] = Yg[row0 * 25 + i];
    __syncthreads();

    int vq = tid / 16;   // 0..15
    int rg = tid % 16;

    const ulonglong2* Wu = (const ulonglong2*)Ws;
    const ulonglong2* Xu = (const ulonglong2*)Xs;

    ull acc[4][4];
#pragma unroll
    for (int c = 0; c < 4; c++)
#pragma unroll
        for (int r = 0; r < 4; r++) acc[c][r] = 0ull;

#pragma unroll 5
    for (int j4 = 0; j4 < 25; j4++) {
        ulonglong2 x0 = Xu[(rg +  0) * 25 + j4];
        ulonglong2 x1 = Xu[(rg + 16) * 25 + j4];
        ulonglong2 x2 = Xu[(rg + 32) * 25 + j4];
        ulonglong2 x3 = Xu[(rg + 48) * 25 + j4];
#pragma unroll
        for (int c = 0; c < 4; c++) {
            ulonglong2 w = Wu[(vq * 4 + c) * 25 + j4];
            fma2(acc[c][0], w.x, x0.x); fma2(acc[c][0], w.y, x0.y);
            fma2(acc[c][1], w.x, x1.x); fma2(acc[c][1], w.y, x1.y);
            fma2(acc[c][2], w.x, x2.x); fma2(acc[c][2], w.y, x2.y);
            fma2(acc[c][3], w.x, x3.x); fma2(acc[c][3], w.y, x3.y);
        }
    }

    int v0 = vq * 4;
    float bb0 = bs[v0], bb1 = bs[v0 + 1], bb2 = bs[v0 + 2], bb3 = bs[v0 + 3];
#pragma unroll
    for (int rr = 0; rr < 4; rr++) {
        size_t row = row0 + rg + 16 * rr;   // = t*BB + b
        size_t t = row >> 9;
        size_t b = row & 511;
        float* o = out + (b * TT + t) * VV + v0;
        o[0] = red2(acc[0][rr]) + bb0;
        o[1] = red2(acc[1][rr]) + bb1;
        if (v0 + 2 < VV) {
            o[2] = red2(acc[2][rr]) + bb2;
            o[3] = red2(acc[3][rr]) + bb3;
        }
    }
}

// ---------------------------------------------------------------------------
extern "C" void kernel_launch(void* const* d_in, const int* in_sizes, int n_in,
                              void* d_out, int out_size) {
    const int*   ids   = (const int*)d_in[0];
    const float* emb   = (const float*)d_in[1];
    const float* W_ih  = (const float*)d_in[2];   // [3][100][100]
    const float* W_hh  = (const float*)d_in[3];   // [3][100][100]
    const float* b_ih  = (const float*)d_in[4];   // [3][100]
    const float* b_hh  = (const float*)d_in[5];   // [3][100]
    const float* W_dec = (const float*)d_in[6];   // [62][100]
    const float* b_dec = (const float*)d_in[7];   // [62]
    float* out = (float*)d_out;

    float *bufA, *bufB;
    cudaGetSymbolAddress((void**)&bufA, g_bufA);
    cudaGetSymbolAddress((void**)&bufB, g_bufB);

    const int proj_smem = 16904 * (int)sizeof(float);   // ~67.6 KB
    const int dec_smem  = 12864 * (int)sizeof(float);   // ~50 KB
    cudaFuncSetAttribute(k_proj, cudaFuncAttributeMaxDynamicSharedMemorySize, proj_smem);
    cudaFuncSetAttribute(k_dec,  cudaFuncAttributeMaxDynamicSharedMemorySize, dec_smem);

    float* hid = out + (size_t)BB * TT * VV;
    const int NPROJ = (TT * BB) / PROJ_ROWS;   // 8192
    const int NDEC  = (TT * BB) / 64;          // 8192

    // gather split into 2 launches (ncu -s5 alignment: idx5 = rnn#2)
    {
        int total = TT * BB * 25;
        int half = total / 2;
        k_gather<<<(half + 255) / 256, 256>>>(ids, emb, bufA, 0);
        k_gather<<<(total - half + 255) / 256, 256>>>(ids, emb, bufA, half);
    }

    // layer 0
    k_proj<<<NPROJ, PROJ_T, proj_smem>>>(bufA, W_ih, b_ih, b_hh, bufB);
    k_rnn<<<BB / 4, 256>>>(bufB, W_hh, hid);
    // layer 1
    k_proj<<<NPROJ, PROJ_T, proj_smem>>>(bufB, W_ih + 10000, b_ih + 100, b_hh + 100, bufA);
    k_rnn<<<BB / 4, 256>>>(bufA, W_hh + 10000, hid + (size_t)BB * HH);
    // layer 2
    k_proj<<<NPROJ, PROJ_T, proj_smem>>>(bufA, W_ih + 20000, b_ih + 200, b_hh + 200, bufB);
    k_rnn<<<BB / 4, 256>>>(bufB, W_hh + 20000, hid + 2 * (size_t)BB * HH);

    k_dec<<<NDEC, 256, dec_smem>>>(bufB, W_dec, b_dec, out);
}

// round 6
// speedup vs baseline: 1.5049x; 1.0158x over previous
#include <cuda_runtime.h>

#define BB 512
#define TT 1024
#define HH 100
#define VV 62

typedef unsigned long long ull;

// ping-pong time-major [T][B][H] activation buffers (no cudaMalloc allowed)
__device__ float g_bufA[(size_t)TT * BB * HH];
__device__ float g_bufB[(size_t)TT * BB * HH];

// packed dual-fp32 FMA: d.lo += a.lo*b.lo ; d.hi += a.hi*b.hi
__device__ __forceinline__ void fma2(ull& d, ull a, ull b) {
    asm("fma.rn.f32x2 %0, %1, %2, %0;" : "+l"(d) : "l"(a), "l"(b));
}
__device__ __forceinline__ float red2(ull v) {
    return __uint_as_float((unsigned)v) + __uint_as_float((unsigned)(v >> 32));
}
// fast tanh: 1 - 2/(e^{2x}+1); __expf saturates to inf -> result -> 1. OK.
__device__ __forceinline__ float ftanh(float x) {
    float e = __expf(x + x);
    return 1.0f - __fdividef(2.0f, e + 1.0f);
}

// ---------------------------------------------------------------------------
// 1) embedding gather (2 launches so ncu -s5 lands on rnn#2):
// ---------------------------------------------------------------------------
__global__ void k_gather(const int* __restrict__ ids,
                         const float* __restrict__ emb,
                         float* __restrict__ out, int base) {
    int idx = base + blockIdx.x * blockDim.x + threadIdx.x;  // T*B*25 f4
    if (idx >= TT * BB * 25) return;
    int c  = idx % 25;
    int tb = idx / 25;
    int b  = tb % BB;
    int t  = tb / BB;
    int id = ids[(size_t)b * TT + t];
    float4 v = ((const float4*)(emb + (size_t)id * HH))[c];
    ((float4*)(out + ((size_t)t * BB + b) * HH))[c] = v;
}

// ---------------------------------------------------------------------------
// 2) input projection: Y[row][k] = sum_j X[row][j]*W[k][j] + bi[k] + bh[k]
// K8 x R2 tile, 64 rows/block, 416 thr (13 warps), OCC 2 (67KB smem).
// kq = tid/32 warp-uniform -> 8 W loads/j4 are warp-broadcasts (1 wf each);
// X loads stride 100 words -> conflict-free. 16 wf : 16 FMA-cyc per j4.
// ---------------------------------------------------------------------------
#define PROJ_T 416
#define PROJ_ROWS 64
__global__ void __launch_bounds__(PROJ_T, 2) k_proj(const float* __restrict__ X,
                                                    const float* __restrict__ W,
                                                    const float* __restrict__ bi,
                                                    const float* __restrict__ bh,
                                                    float* __restrict__ Y) {
    extern __shared__ float sm[];
    float* Ws = sm;             // [104][100] zero-padded rows 100..103
    float* Xs = sm + 10400;     // [64][100]
    float* bs = sm + 16800;     // [104]

    int tid = threadIdx.x;
    float4* Ws4 = (float4*)Ws;
    const float4* Wg = (const float4*)W;
    for (int i = tid; i < 2600; i += PROJ_T) {      // 104*25
        int k = i / 25;
        float4 z = {0.f, 0.f, 0.f, 0.f};
        Ws4[i] = (k < HH) ? Wg[i] : z;
    }
    if (tid < 104) bs[tid] = (tid < HH) ? (bi[tid] + bh[tid]) : 0.f;

    size_t row0 = (size_t)blockIdx.x * PROJ_ROWS;
    float4* Xs4 = (float4*)Xs;
    const float4* Xg = (const float4*)X;
    for (int i = tid; i < PROJ_ROWS * 25; i += PROJ_T) Xs4[i] = Xg[row0 * 25 + i];
    __syncthreads();

    int kq = tid / 32;          // 0..12, warp-uniform
    int rg = tid % 32;
    int k0 = kq * 8;

    const ulonglong2* Wu = (const ulonglong2*)Ws;   // 25 pairs per k-row
    const ulonglong2* Xu = (const ulonglong2*)Xs;

    ull acc[8][2];
#pragma unroll
    for (int c = 0; c < 8; c++) { acc[c][0] = 0ull; acc[c][1] = 0ull; }

#pragma unroll 5
    for (int j4 = 0; j4 < 25; j4++) {
        ulonglong2 x0 = Xu[(rg +  0) * 25 + j4];
        ulonglong2 x1 = Xu[(rg + 32) * 25 + j4];
#pragma unroll
        for (int c = 0; c < 8; c++) {
            ulonglong2 w = Wu[(k0 + c) * 25 + j4];  // warp-broadcast
            fma2(acc[c][0], w.x, x0.x); fma2(acc[c][0], w.y, x0.y);
            fma2(acc[c][1], w.x, x1.x); fma2(acc[c][1], w.y, x1.y);
        }
    }

    float bb[8];
#pragma unroll
    for (int c = 0; c < 8; c++) bb[c] = bs[k0 + c];

    float4* Yg = (float4*)Y;
#pragma unroll
    for (int rr = 0; rr < 2; rr++) {
        size_t row = row0 + rg + 32 * rr;
        float4 o;
        o.x = red2(acc[0][rr]) + bb[0];
        o.y = red2(acc[1][rr]) + bb[1];
        o.z = red2(acc[2][rr]) + bb[2];
        o.w = red2(acc[3][rr]) + bb[3];
        Yg[row * 25 + kq * 2] = o;
        if (kq < 12) {
            float4 o2;
            o2.x = red2(acc[4][rr]) + bb[4];
            o2.y = red2(acc[5][rr]) + bb[5];
            o2.z = red2(acc[6][rr]) + bb[6];
            o2.w = red2(acc[7][rr]) + bb[7];
            Yg[row * 25 + kq * 2 + 1] = o2;
        }
    }
}

// ---------------------------------------------------------------------------
// 3) recurrent scan: h_new = tanh(xin[t] + h @ Wh^T), in-place on XY.
// 128 blocks (exactly 1/SM) x 256 threads = two independent 128-thread
// groups, each owning 2 batch rows -> 4 rows/block, 8 warps/SM, balanced.
// Thread k holds W[k][:] in 100 regs; h via smem broadcast; 1 barrier/step.
// ---------------------------------------------------------------------------
__global__ void __launch_bounds__(256, 1) k_rnn(float* __restrict__ XY,
                                                const float* __restrict__ W,
                                                float* __restrict__ hout) {
    __shared__ __align__(16) float hs[2][4][104];

    int tid = threadIdx.x;
    int g   = tid >> 7;          // row-group 0/1
    int k   = tid & 127;
    int kk  = (k < HH) ? k : (HH - 1);
    int r0  = g * 2;

    ulonglong2 wv[25];           // W[kk][0..99]
    const ulonglong2* Wg = (const ulonglong2*)W;
#pragma unroll
    for (int i = 0; i < 25; i++) wv[i] = Wg[kk * 25 + i];

    if (tid < 104) {
        hs[0][0][tid] = 0.f; hs[0][1][tid] = 0.f;
        hs[0][2][tid] = 0.f; hs[0][3][tid] = 0.f;
    }
    __syncthreads();

    int b0 = blockIdx.x * 4 + r0;            // this group's first batch row
    const size_t st = (size_t)BB * HH;
    const float* px = XY + (size_t)b0 * HH + kk;

    float c0 = px[0], c1 = px[HH];
    int p = 0;

    for (int t = 0; t < TT; t++) {
        size_t tn = (size_t)((t + 1 < TT) ? t + 1 : t) * st;
        float n0 = px[tn], n1 = px[tn + HH];  // prefetch next xin

        ull a0l = 0, a0h = 0, a1l = 0, a1h = 0;
        const ulonglong2* h0p = (const ulonglong2*)&hs[p][r0][0];
        const ulonglong2* h1p = (const ulonglong2*)&hs[p][r0 + 1][0];
#pragma unroll
        for (int j = 0; j < 25; j++) {
            ulonglong2 w  = wv[j];
            ulonglong2 h0 = h0p[j];           // broadcast loads
            ulonglong2 h1 = h1p[j];
            fma2(a0l, w.x, h0.x); fma2(a0h, w.y, h0.y);
            fma2(a1l, w.x, h1.x); fma2(a1h, w.y, h1.y);
        }
        float z0 = ftanh(red2(a0l) + red2(a0h) + c0);
        float z1 = ftanh(red2(a1l) + red2(a1h) + c1);

        if (k < HH) {
            hs[p ^ 1][r0][k]     = z0;
            hs[p ^ 1][r0 + 1][k] = z1;
            float* py = XY + (size_t)t * st + (size_t)b0 * HH + k;
            py[0] = z0; py[HH] = z1;
        }
        __syncthreads();
        p ^= 1;
        c0 = n0; c1 = n1;
    }

    if (k < HH) {
        hout[(size_t)b0 * HH + k]       = hs[p][r0][k];
        hout[(size_t)(b0 + 1) * HH + k] = hs[p][r0 + 1][k];
    }
}

// ---------------------------------------------------------------------------
// 4) decoder: logits[b][t][v] = dot(ys[t][b][:], Wd[v][:]) + bd[v]
// 256 thr = 16 v-quads (vq=tid/16, V padded 64) x 16 row-groups, 64 rows/blk.
// ---------------------------------------------------------------------------
__global__ void __launch_bounds__(256, 3) k_dec(const float* __restrict__ Ys,
                                                const float* __restrict__ Wd,
                                                const float* __restrict__ bd,
                                                float* __restrict__ out) {
    extern __shared__ float sm[];
    float* Ws = sm;            // [64][100] zero-padded
    float* Xs = sm + 6400;     // [64][100]
    float* bs = sm + 12800;    // [64]

    int tid = threadIdx.x;
    for (int i = tid; i < 6400; i += 256) Ws[i] = (i < VV * HH) ? Wd[i] : 0.f;
    if (tid < 64) bs[tid] = (tid < VV) ? bd[tid] : 0.f;

    size_t row0 = (size_t)blockIdx.x * 64;
    float4* Xs4 = (float4*)Xs;
    const float4* Yg = (const float4*)Ys;
    for (int i = tid; i < 1600; i += 256) Xs4[i] = Yg[row0 * 25 + i];
    __syncthreads();

    int vq = tid / 16;   // 0..15
    int rg = tid % 16;

    const ulonglong2* Wu = (const ulonglong2*)Ws;
    const ulonglong2* Xu = (const ulonglong2*)Xs;

    ull acc[4][4];
#pragma unroll
    for (int c = 0; c < 4; c++)
#pragma unroll
        for (int r = 0; r < 4; r++) acc[c][r] = 0ull;

#pragma unroll 5
    for (int j4 = 0; j4 < 25; j4++) {
        ulonglong2 x0 = Xu[(rg +  0) * 25 + j4];
        ulonglong2 x1 = Xu[(rg + 16) * 25 + j4];
        ulonglong2 x2 = Xu[(rg + 32) * 25 + j4];
        ulonglong2 x3 = Xu[(rg + 48) * 25 + j4];
#pragma unroll
        for (int c = 0; c < 4; c++) {
            ulonglong2 w = Wu[(vq * 4 + c) * 25 + j4];
            fma2(acc[c][0], w.x, x0.x); fma2(acc[c][0], w.y, x0.y);
            fma2(acc[c][1], w.x, x1.x); fma2(acc[c][1], w.y, x1.y);
            fma2(acc[c][2], w.x, x2.x); fma2(acc[c][2], w.y, x2.y);
            fma2(acc[c][3], w.x, x3.x); fma2(acc[c][3], w.y, x3.y);
        }
    }

    int v0 = vq * 4;
    float bb0 = bs[v0], bb1 = bs[v0 + 1], bb2 = bs[v0 + 2], bb3 = bs[v0 + 3];
#pragma unroll
    for (int rr = 0; rr < 4; rr++) {
        size_t row = row0 + rg + 16 * rr;   // = t*BB + b
        size_t t = row >> 9;
        size_t b = row & 511;
        float* o = out + (b * TT + t) * VV + v0;
        o[0] = red2(acc[0][rr]) + bb0;
        o[1] = red2(acc[1][rr]) + bb1;
        if (v0 + 2 < VV) {
            o[2] = red2(acc[2][rr]) + bb2;
            o[3] = red2(acc[3][rr]) + bb3;
        }
    }
}

// ---------------------------------------------------------------------------
extern "C" void kernel_launch(void* const* d_in, const int* in_sizes, int n_in,
                              void* d_out, int out_size) {
    const int*   ids   = (const int*)d_in[0];
    const float* emb   = (const float*)d_in[1];
    const float* W_ih  = (const float*)d_in[2];   // [3][100][100]
    const float* W_hh  = (const float*)d_in[3];   // [3][100][100]
    const float* b_ih  = (const float*)d_in[4];   // [3][100]
    const float* b_hh  = (const float*)d_in[5];   // [3][100]
    const float* W_dec = (const float*)d_in[6];   // [62][100]
    const float* b_dec = (const float*)d_in[7];   // [62]
    float* out = (float*)d_out;

    float *bufA, *bufB;
    cudaGetSymbolAddress((void**)&bufA, g_bufA);
    cudaGetSymbolAddress((void**)&bufB, g_bufB);

    const int proj_smem = 16904 * (int)sizeof(float);   // ~67.6 KB
    const int dec_smem  = 12864 * (int)sizeof(float);   // ~50 KB
    cudaFuncSetAttribute(k_proj, cudaFuncAttributeMaxDynamicSharedMemorySize, proj_smem);
    cudaFuncSetAttribute(k_dec,  cudaFuncAttributeMaxDynamicSharedMemorySize, dec_smem);

    float* hid = out + (size_t)BB * TT * VV;
    const int NPROJ = (TT * BB) / PROJ_ROWS;   // 8192
    const int NDEC  = (TT * BB) / 64;          // 8192

    // gather split into 2 launches (ncu -s5 alignment: idx5 = rnn#2)
    {
        int total = TT * BB * 25;
        int half = total / 2;
        k_gather<<<(half + 255) / 256, 256>>>(ids, emb, bufA, 0);
        k_gather<<<(total - half + 255) / 256, 256>>>(ids, emb, bufA, half);
    }

    // layer 0
    k_proj<<<NPROJ, PROJ_T, proj_smem>>>(bufA, W_ih, b_ih, b_hh, bufB);
    k_rnn<<<BB / 4, 256>>>(bufB, W_hh, hid);
    // layer 1
    k_proj<<<NPROJ, PROJ_T, proj_smem>>>(bufB, W_ih + 10000, b_ih + 100, b_hh + 100, bufA);
    k_rnn<<<BB / 4, 256>>>(bufA, W_hh + 10000, hid + (size_t)BB * HH);
    // layer 2
    k_proj<<<NPROJ, PROJ_T, proj_smem>>>(bufA, W_ih + 20000, b_ih + 200, b_hh + 200, bufB);
    k_rnn<<<BB / 4, 256>>>(bufB, W_hh + 20000, hid + 2 * (size_t)BB * HH);

    k_dec<<<NDEC, 256, dec_smem>>>(bufB, W_dec, b_dec, out);
}